// round 4
// baseline (speedup 1.0000x reference)
#include <cuda_runtime.h>
#include <cstdint>

#define BDIM   128
#define BATCH  32
#define SEQ    512
#define LAB    64
#define START_ 61
#define STOP_  62
#define CHUNK  64

#define FMA2(d,a,b,c)  asm("fma.rn.f32x2 %0, %1, %2, %3;" : "=l"(d) : "l"(a), "l"(b), "l"(c))
#define ADD2(d,a,b)    asm("add.rn.f32x2 %0, %1, %2;"     : "=l"(d) : "l"(a), "l"(b))
#define PACK2(d,lo,hi) asm("mov.b64 %0, {%1, %2};"        : "=l"(d) : "f"(lo), "f"(hi))
#define UNPACK2(lo,hi,s) asm("mov.b64 {%0, %1}, %2;"      : "=f"(lo), "=f"(hi) : "l"(s))

__global__ __launch_bounds__(BDIM, 1)
void crf_fwd_kernel(const float* __restrict__ enc,   // [B,S,L]
                    const float* __restrict__ T,     // [L,L]
                    const int*   __restrict__ lens,  // [B]
                    const int*   __restrict__ tags,  // [B,S]
                    float*       __restrict__ out)   // [2*B]
{
    __shared__ __align__(16) float e_sh[2][CHUNK * LAB];  // enc chunk double buffer
    __shared__ __align__(16) float p_sh[2][72];           // p[0..31] @ [0..31], p[32..63] @ [36..67]
    __shared__ float vred[LAB];
    __shared__ float redw[4];

    const int b   = blockIdx.x;
    const int tid = threadIdx.x;
    const int j   = tid >> 1;      // label column 0..63
    const int g   = tid & 1;       // which 32-row half of the i-reduction
    const int len = lens[b];
    const float* encb = enc + (size_t)b * SEQ * LAB;
    const int idx = (j < 32) ? j : j + 4;   // padded store slot for column j

    // ---- prefetch enc chunks 0 and 1 (one cp.async group each) ----
    #pragma unroll
    for (int c = 0; c < 2; ++c) {
        const float* src = encb + c * CHUNK * LAB + tid * 4;
        uint32_t dst = (uint32_t)__cvta_generic_to_shared(&e_sh[c][tid * 4]);
        #pragma unroll
        for (int k = 0; k < 8; ++k)
            asm volatile("cp.async.cg.shared.global [%0], [%1], 16;\n"
                         :: "r"(dst + k * BDIM * 16), "l"(src + k * BDIM * 4));
        asm volatile("cp.async.commit_group;\n");
    }

    // ---- E column j, rows [g*32, g*32+32), packed as 16 f32x2 pairs ----
    unsigned long long E2[16];
    #pragma unroll
    for (int k = 0; k < 16; ++k) {
        float lo = expf(T[(g * 32 + 2 * k)     * LAB + j]);  // exp(NEG) == 0 exactly
        float hi = expf(T[(g * 32 + 2 * k + 1) * LAB + j]);
        PACK2(E2[k], lo, hi);
    }

    asm volatile("cp.async.wait_group 1;\n");    // chunk 0 resident
    __syncthreads();

    if (g == 0)
        p_sh[0][idx] = expf(T[START_ * LAB + j] + e_sh[0][j]);

    int Mi = 0;                                  // accumulated log2 scale (g==0 threads)
    __syncthreads();

    const int nch = ((len - 1) >> 6) + 1;        // chunks containing steps 1..len-1
    int t = 1;

    for (int c = 0; c < nch; ++c) {
        if (c >= 1) {
            const int nc = c + 1;
            if (nc < nch) {                      // prefetch chunk c+1
                const float* src = encb + nc * CHUNK * LAB + tid * 4;
                uint32_t dst = (uint32_t)__cvta_generic_to_shared(
                                   &e_sh[nc & 1][tid * 4]);
                #pragma unroll
                for (int k = 0; k < 8; ++k)
                    asm volatile("cp.async.cg.shared.global [%0], [%1], 16;\n"
                                 :: "r"(dst + k * BDIM * 16), "l"(src + k * BDIM * 4));
                asm volatile("cp.async.commit_group;\n");
                asm volatile("cp.async.wait_group 1;\n");   // chunk c resident
            } else {
                asm volatile("cp.async.wait_group 0;\n");
            }
            __syncthreads();
        }

        const float* eb = e_sh[c & 1];
        const int tt0   = t - c * CHUNK;                 // 1 for c==0, else 0
        const int ttend = min(CHUNK, len - c * CHUNK);   // steps with t < len

        // pipeline prologue: u for the first step of this chunk (g==0 only)
        float u = (g == 0) ? __expf(eb[tt0 * LAB + j]) : 0.0f;

        #pragma unroll 4
        for (int tt = tt0; tt < ttend; ++tt, ++t) {
            const float* pp = &p_sh[(t - 1) & 1][0];
            const ulonglong2* pv =
                reinterpret_cast<const ulonglong2*>(pp + g * 36);

            // issue all 8 LDS.128 up front (MLP)
            ulonglong2 v0 = pv[0], v1 = pv[1], v2 = pv[2], v3 = pv[3];
            ulonglong2 v4 = pv[4], v5 = pv[5], v6 = pv[6], v7 = pv[7];

            unsigned long long a0 = 0, a1 = 0, a2 = 0, a3 = 0;
            FMA2(a0, v0.x, E2[ 0], a0); FMA2(a1, v0.y, E2[ 1], a1);
            FMA2(a2, v1.x, E2[ 2], a2); FMA2(a3, v1.y, E2[ 3], a3);
            FMA2(a0, v2.x, E2[ 4], a0); FMA2(a1, v2.y, E2[ 5], a1);
            FMA2(a2, v3.x, E2[ 6], a2); FMA2(a3, v3.y, E2[ 7], a3);
            FMA2(a0, v4.x, E2[ 8], a0); FMA2(a1, v4.y, E2[ 9], a1);
            FMA2(a2, v5.x, E2[10], a2); FMA2(a3, v5.y, E2[11], a3);
            FMA2(a0, v6.x, E2[12], a0); FMA2(a1, v6.y, E2[13], a1);
            FMA2(a2, v7.x, E2[14], a2); FMA2(a3, v7.y, E2[15], a3);

            unsigned long long s01, s23, s;
            ADD2(s01, a0, a1);
            ADD2(s23, a2, a3);
            ADD2(s, s01, s23);
            float lo, hi;
            UNPACK2(lo, hi, s);
            float q = lo + hi;
            q += __shfl_xor_sync(0xffffffffu, q, 1);     // merge the two halves

            if (g == 0) {
                // exact 2^-e0 rescale derived from p[0] (low word of v0.x),
                // uniform across all g==0 threads (same broadcast LDS value)
                unsigned int p0b = (unsigned int)v0.x;
                int   e0 = (int)((p0b >> 23) & 255u) - 127;
                float sc = __int_as_float((127 - e0) << 23);
                Mi += e0;
                p_sh[t & 1][idx] = q * u * sc;
                // pipeline: next step's u before the barrier
                int ttn = (tt + 1 < ttend) ? tt + 1 : tt;
                u = __expf(eb[ttn * LAB + j]);
            }
            __syncthreads();
        }
    }

    // ================= epilogue =================
    const int lastbuf = (len - 1) & 1;
    if (g == 0)
        vred[j] = p_sh[lastbuf][idx] * expf(T[j * LAB + STOP_]);

    // labeled score: strided gather-sum over t
    float lsum = 0.0f;
    const int* tagb = tags + b * SEQ;
    for (int t2 = 1 + tid; t2 < len; t2 += BDIM) {
        int tg = tagb[t2], tp = tagb[t2 - 1];
        lsum += T[tp * LAB + tg] + encb[t2 * LAB + tg];
    }
    #pragma unroll
    for (int m = 16; m; m >>= 1)
        lsum += __shfl_xor_sync(0xffffffffu, lsum, m);
    if ((tid & 31) == 0) redw[tid >> 5] = lsum;
    __syncthreads();

    if (tid == 0) {
        float ssum = 0.0f;
        #pragma unroll
        for (int k = 0; k < LAB; ++k) ssum += vred[k];
        out[b] = (float)((double)Mi * 0.6931471805599453 + (double)logf(ssum));

        int t0g = tagb[0];
        int eg  = tagb[len - 1];
        out[BATCH + b] = redw[0] + redw[1] + redw[2] + redw[3]
                       + T[START_ * LAB + t0g] + encb[t0g]
                       + T[eg * LAB + STOP_];
    }
}

extern "C" void kernel_launch(void* const* d_in, const int* in_sizes, int n_in,
                              void* d_out, int out_size)
{
    const float* enc  = (const float*)d_in[0];   // encoder_scores [32,512,64]
    const float* T    = (const float*)d_in[1];   // transition [64,64]
    const int*   lens = (const int*)  d_in[2];   // word_seq_lens [32]
    const int*   tags = (const int*)  d_in[3];   // tags [32,512]
    // d_in[4] = mask — recomputed from lens, unused
    float* out = (float*)d_out;                  // [64]: unlabeled(32) ++ labeled(32)

    crf_fwd_kernel<<<BATCH, BDIM>>>(enc, T, lens, tags, out);
}

// round 5
// speedup vs baseline: 1.4610x; 1.4610x over previous
#include <cuda_runtime.h>
#include <cstdint>

#define BDIM   64
#define BATCH  32
#define SEQ    512
#define LAB    64
#define START_ 61
#define STOP_  62
#define CHUNK  64

#define FMA2(d,a,b,c)  asm("fma.rn.f32x2 %0, %1, %2, %3;" : "=l"(d) : "l"(a), "l"(b), "l"(c))
#define ADD2(d,a,b)    asm("add.rn.f32x2 %0, %1, %2;"     : "=l"(d) : "l"(a), "l"(b))
#define PACK2(d,lo,hi) asm("mov.b64 %0, {%1, %2};"        : "=l"(d) : "f"(lo), "f"(hi))
#define UNPACK2(lo,hi,s) asm("mov.b64 {%0, %1}, %2;"      : "=f"(lo), "=f"(hi) : "l"(s))

__global__ __launch_bounds__(BDIM, 1)
void crf_fwd_kernel(const float* __restrict__ enc,   // [B,S,L]
                    const float* __restrict__ T,     // [L,L]
                    const int*   __restrict__ lens,  // [B]
                    const int*   __restrict__ tags,  // [B,S]
                    float*       __restrict__ out)   // [2*B]
{
    __shared__ __align__(16) float e_sh[2][CHUNK * LAB];  // enc chunk double buffer
    __shared__ __align__(16) float p_sh[2][LAB];          // alpha (linear, scaled)
    __shared__ float redu[2], redl[2];

    const int b   = blockIdx.x;
    const int tid = threadIdx.x;          // == label column j (0..63)
    const int len = lens[b];
    const float* encb = enc + (size_t)b * SEQ * LAB;

    // ---- prefetch enc chunks 0 and 1 (one cp.async group each) ----
    #pragma unroll
    for (int c = 0; c < 2; ++c) {
        const float* src = encb + c * CHUNK * LAB + tid * 4;
        uint32_t dst = (uint32_t)__cvta_generic_to_shared(&e_sh[c][tid * 4]);
        #pragma unroll
        for (int k = 0; k < 16; ++k)
            asm volatile("cp.async.cg.shared.global [%0], [%1], 16;\n"
                         :: "r"(dst + k * BDIM * 16), "l"(src + k * BDIM * 4));
        asm volatile("cp.async.commit_group;\n");
    }

    // ---- full E column j in registers, packed as 32 f32x2 pairs ----
    unsigned long long E2[32];
    #pragma unroll
    for (int k = 0; k < 32; ++k) {
        float lo = expf(T[(2 * k)     * LAB + tid]);  // exp(NEG) == 0 exactly
        float hi = expf(T[(2 * k + 1) * LAB + tid]);
        PACK2(E2[k], lo, hi);
    }

    asm volatile("cp.async.wait_group 1;\n");    // chunk 0 resident
    __syncthreads();

    p_sh[0][tid] = expf(T[START_ * LAB + tid] + e_sh[0][tid]);

    int Mi = 0;                                  // accumulated log2 scale (uniform)
    __syncthreads();

    const int nch = ((len - 1) >> 6) + 1;        // chunks containing steps 1..len-1
    int t = 1;

    for (int c = 0; c < nch; ++c) {
        if (c >= 1) {
            const int nc = c + 1;
            if (nc < nch) {                      // prefetch chunk c+1
                const float* src = encb + nc * CHUNK * LAB + tid * 4;
                uint32_t dst = (uint32_t)__cvta_generic_to_shared(
                                   &e_sh[nc & 1][tid * 4]);
                #pragma unroll
                for (int k = 0; k < 16; ++k)
                    asm volatile("cp.async.cg.shared.global [%0], [%1], 16;\n"
                                 :: "r"(dst + k * BDIM * 16), "l"(src + k * BDIM * 4));
                asm volatile("cp.async.commit_group;\n");
                asm volatile("cp.async.wait_group 1;\n");   // chunk c resident
            } else {
                asm volatile("cp.async.wait_group 0;\n");
            }
            __syncthreads();
        }

        const float* eb = e_sh[c & 1];
        const int tt0   = t - c * CHUNK;                 // 1 for c==0, else 0
        const int ttend = min(CHUNK, len - c * CHUNK);   // steps with t < len

        #pragma unroll 4
        for (int tt = tt0; tt < ttend; ++tt, ++t) {
            // u = exp(enc[t,j]) — independent of p; overlaps the FMA chain
            float u = __expf(eb[tt * LAB + tid]);

            const ulonglong2* pv =
                reinterpret_cast<const ulonglong2*>(&p_sh[(t - 1) & 1][0]);

            // full 64-wide dot product: 16 broadcast LDS.128, 32 packed FMAs
            unsigned long long a0 = 0, a1 = 0, a2 = 0, a3 = 0;
            ulonglong2 v0 = pv[0];
            #pragma unroll
            for (int k = 0; k < 16; ++k) {
                ulonglong2 v = (k == 0) ? v0 : pv[k];
                if (k & 1) { FMA2(a2, v.x, E2[2 * k], a2); FMA2(a3, v.y, E2[2 * k + 1], a3); }
                else       { FMA2(a0, v.x, E2[2 * k], a0); FMA2(a1, v.y, E2[2 * k + 1], a1); }
            }
            unsigned long long s01, s23, s;
            ADD2(s01, a0, a1);
            ADD2(s23, a2, a3);
            ADD2(s, s01, s23);
            float lo, hi;
            UNPACK2(lo, hi, s);
            float q = lo + hi;

            // exact 2^-e0 rescale from p[0] (low word of v0.x, broadcast-uniform)
            unsigned int p0b = (unsigned int)v0.x;
            int   e0 = (int)((p0b >> 23) & 255u) - 127;
            float sc = __int_as_float((127 - e0) << 23);
            Mi += e0;

            p_sh[t & 1][tid] = q * u * sc;
            __syncthreads();
        }
    }

    // ================= epilogue =================
    const int lastbuf = (len - 1) & 1;
    float vterm = p_sh[lastbuf][tid] * expf(T[tid * LAB + STOP_]);
    #pragma unroll
    for (int m = 16; m; m >>= 1)
        vterm += __shfl_xor_sync(0xffffffffu, vterm, m);

    // labeled score: strided gather-sum over t
    float lsum = 0.0f;
    const int* tagb = tags + b * SEQ;
    for (int t2 = 1 + tid; t2 < len; t2 += BDIM) {
        int tg = tagb[t2], tp = tagb[t2 - 1];
        lsum += T[tp * LAB + tg] + encb[t2 * LAB + tg];
    }
    #pragma unroll
    for (int m = 16; m; m >>= 1)
        lsum += __shfl_xor_sync(0xffffffffu, lsum, m);

    if ((tid & 31) == 0) {
        redu[tid >> 5] = vterm;
        redl[tid >> 5] = lsum;
    }
    __syncthreads();

    if (tid == 0) {
        float ssum = redu[0] + redu[1];
        out[b] = (float)((double)Mi * 0.6931471805599453 + (double)logf(ssum));

        int t0g = tagb[0];
        int eg  = tagb[len - 1];
        out[BATCH + b] = redl[0] + redl[1]
                       + T[START_ * LAB + t0g] + encb[t0g]
                       + T[eg * LAB + STOP_];
    }
}

extern "C" void kernel_launch(void* const* d_in, const int* in_sizes, int n_in,
                              void* d_out, int out_size)
{
    const float* enc  = (const float*)d_in[0];   // encoder_scores [32,512,64]
    const float* T    = (const float*)d_in[1];   // transition [64,64]
    const int*   lens = (const int*)  d_in[2];   // word_seq_lens [32]
    const int*   tags = (const int*)  d_in[3];   // tags [32,512]
    // d_in[4] = mask — recomputed from lens, unused
    float* out = (float*)d_out;                  // [64]: unlabeled(32) ++ labeled(32)

    crf_fwd_kernel<<<BATCH, BDIM>>>(enc, T, lens, tags, out);
}

// round 7
// speedup vs baseline: 1.9327x; 1.3228x over previous
#include <cuda_runtime.h>
#include <cstdint>

#define BATCH  32
#define SEQ    512
#define LAB    64
#define START_ 61
#define STOP_  62
#define CH     32          // enc chunk rows per cp.async stage

#define FMA2(d,a,b,c)  asm("fma.rn.f32x2 %0, %1, %2, %3;" : "=l"(d) : "l"(a), "l"(b), "l"(c))
#define ADD2(d,a,b)    asm("add.rn.f32x2 %0, %1, %2;"     : "=l"(d) : "l"(a), "l"(b))
#define PACK2(d,lo,hi) asm("mov.b64 %0, {%1, %2};"        : "=l"(d) : "f"(lo), "f"(hi))
#define UNPACK2(lo,hi,s) asm("mov.b64 {%0, %1}, %2;"      : "=f"(lo), "=f"(hi) : "l"(s))
#define BARF() asm volatile("bar.sync 1, 128;" ::: "memory")
#define BARB() asm volatile("bar.sync 2, 128;" ::: "memory")
#define CPA(dst,src) asm volatile("cp.async.cg.shared.global [%0], [%1], 16;\n" :: "r"(dst), "l"(src))
#define CPC() asm volatile("cp.async.commit_group;\n")
#define CPW1() asm volatile("cp.async.wait_group 1;\n")
#define CPW0() asm volatile("cp.async.wait_group 0;\n")

// one full 64-wide half-dot step: 8 LDS.128 + 16 FMA2 + tree + shfl merge
#define DOT_BODY(PV, Q, V0X)                                              \
    ulonglong2 v0 = (PV)[0], v1 = (PV)[1], v2 = (PV)[2], v3 = (PV)[3];    \
    ulonglong2 v4 = (PV)[4], v5 = (PV)[5], v6 = (PV)[6], v7 = (PV)[7];    \
    unsigned long long a0 = 0, a1 = 0, a2 = 0, a3 = 0;                    \
    FMA2(a0, v0.x, E2[ 0], a0); FMA2(a1, v0.y, E2[ 1], a1);               \
    FMA2(a2, v1.x, E2[ 2], a2); FMA2(a3, v1.y, E2[ 3], a3);               \
    FMA2(a0, v2.x, E2[ 4], a0); FMA2(a1, v2.y, E2[ 5], a1);               \
    FMA2(a2, v3.x, E2[ 6], a2); FMA2(a3, v3.y, E2[ 7], a3);               \
    FMA2(a0, v4.x, E2[ 8], a0); FMA2(a1, v4.y, E2[ 9], a1);               \
    FMA2(a2, v5.x, E2[10], a2); FMA2(a3, v5.y, E2[11], a3);               \
    FMA2(a0, v6.x, E2[12], a0); FMA2(a1, v6.y, E2[13], a1);               \
    FMA2(a2, v7.x, E2[14], a2); FMA2(a3, v7.y, E2[15], a3);               \
    unsigned long long s01, s23, sT;                                      \
    ADD2(s01, a0, a1); ADD2(s23, a2, a3); ADD2(sT, s01, s23);             \
    float qlo, qhi; UNPACK2(qlo, qhi, sT);                                \
    float Q = qlo + qhi;                                                  \
    Q += __shfl_xor_sync(0xffffffffu, Q, 1);                              \
    (void)(V0X)

__global__ __launch_bounds__(256, 1)
void crf_fwd_kernel(const float* __restrict__ enc,   // [B,S,L]
                    const float* __restrict__ T,     // [L,L]
                    const int*   __restrict__ lens,  // [B]
                    const int*   __restrict__ tags,  // [B,S]
                    float*       __restrict__ out)   // [2*B]
{
    __shared__ __align__(16) float e_f[2][CH * LAB];   // fwd enc chunks
    __shared__ __align__(16) float e_b[2][CH * LAB];   // bwd enc chunks
    __shared__ __align__(16) float p_f[2][72];         // alpha (scaled), padded halves
    __shared__ __align__(16) float p_b[2][72];         // z (scaled), padded halves
    __shared__ float du[2];                            // combine-dot partials
    __shared__ float lred[8];
    __shared__ int   mif_sh, mib_sh;

    const int b    = blockIdx.x;
    const int tid  = threadIdx.x;
    const int len  = lens[b];
    const int mid  = (len - 1) >> 1;                   // fwd: t=1..mid, bwd: s=len-2..mid
    const float* encb = enc + (size_t)b * SEQ * LAB;

    const int ltid = tid & 127;
    const int j    = ltid >> 1;                        // column (fwd) / row (bwd)
    const int g    = ltid & 1;                         // half of the reduction
    const int idx  = (j < 32) ? j : j + 4;             // padded store slot

    if (tid < 128) {
        // ===================== FORWARD: p_t = D_{u_t} E^T p_{t-1} =====================
        #pragma unroll
        for (int c = 0; c < 2; ++c) {
            const float* src = encb + c * CH * LAB + ltid * 4;
            uint32_t dst = (uint32_t)__cvta_generic_to_shared(&e_f[c][ltid * 4]);
            #pragma unroll
            for (int k = 0; k < 4; ++k) CPA(dst + k * 2048, src + k * 512);
            CPC();
        }

        unsigned long long E2[16];                     // E column j, rows [g*32,+32)
        #pragma unroll
        for (int k = 0; k < 16; ++k) {
            float lo = expf(T[(g * 32 + 2 * k)     * LAB + j]);
            float hi = expf(T[(g * 32 + 2 * k + 1) * LAB + j]);
            PACK2(E2[k], lo, hi);
        }

        CPW1();
        BARF();
        if (g == 0) p_f[0][idx] = expf(T[START_ * LAB + j] + e_f[0][j]);
        int Mi = 0;
        BARF();

        const int nch = (mid >> 5) + 1;
        int t = 1;
        for (int c = 0; c < nch; ++c) {
            if (c >= 1) {
                if (c + 1 < nch) {
                    const float* src = encb + (c + 1) * CH * LAB + ltid * 4;
                    uint32_t dst = (uint32_t)__cvta_generic_to_shared(
                                       &e_f[(c + 1) & 1][ltid * 4]);
                    #pragma unroll
                    for (int k = 0; k < 4; ++k) CPA(dst + k * 2048, src + k * 512);
                    CPC(); CPW1();
                } else CPW0();
                BARF();
            }
            const float* eb = e_f[c & 1];
            const int tt0   = t - c * CH;
            const int ttend = min(CH, mid + 1 - c * CH);
            #pragma unroll 4
            for (int tt = tt0; tt < ttend; ++tt, ++t) {
                const float* pp = &p_f[(t - 1) & 1][0];
                float u  = __expf(eb[tt * LAB + j]);
                float p0 = pp[0];                              // broadcast LDS
                int   e0 = ((__float_as_int(p0) >> 23) & 255) - 127;
                float sc = __int_as_float((127 - e0) << 23);   // exact 2^-e0
                Mi += e0;
                float us = u * sc;
                const ulonglong2* pv =
                    reinterpret_cast<const ulonglong2*>(pp + g * 36);
                DOT_BODY(pv, q, v0.x);
                if (g == 0) p_f[t & 1][idx] = q * us;
                BARF();
            }
        }
        if (tid == 0) mif_sh = Mi;                     // single writer
    } else {
        // ===================== BACKWARD: z_s = D_{u_s} E z_{s+1} =====================
        const int chi = (len - 2) >> 5;
        const int clo = mid >> 5;
        {
            const float* src = encb + chi * CH * LAB + ltid * 4;
            uint32_t dst = (uint32_t)__cvta_generic_to_shared(&e_b[chi & 1][ltid * 4]);
            #pragma unroll
            for (int k = 0; k < 4; ++k) CPA(dst + k * 2048, src + k * 512);
            CPC();
        }
        if (chi - 1 >= clo) {
            const float* src = encb + (chi - 1) * CH * LAB + ltid * 4;
            uint32_t dst = (uint32_t)__cvta_generic_to_shared(&e_b[(chi - 1) & 1][ltid * 4]);
            #pragma unroll
            for (int k = 0; k < 4; ++k) CPA(dst + k * 2048, src + k * 512);
            CPC();
        }

        unsigned long long E2[16];                     // E row j, cols [g*32,+32)
        #pragma unroll
        for (int k = 0; k < 16; ++k) {
            float lo = expf(T[j * LAB + g * 32 + 2 * k]);
            float hi = expf(T[j * LAB + g * 32 + 2 * k + 1]);
            PACK2(E2[k], lo, hi);
        }

        // z_{len-1}[i] = exp(T[i][STOP]) * exp(enc[len-1][i])
        if (g == 0)
            p_b[(len - 1) & 1][idx] =
                expf(T[j * LAB + STOP_]) * __expf(encb[(size_t)(len - 1) * LAB + j]);
        int Mi = 0;
        if (chi - 1 >= clo) CPW1(); else CPW0();
        BARB();

        int s = len - 2;
        for (int c = chi; c >= clo; --c) {
            if (c < chi) {
                if (c - 1 >= clo) {
                    const float* src = encb + (c - 1) * CH * LAB + ltid * 4;
                    uint32_t dst = (uint32_t)__cvta_generic_to_shared(
                                       &e_b[(c - 1) & 1][ltid * 4]);
                    #pragma unroll
                    for (int k = 0; k < 4; ++k) CPA(dst + k * 2048, src + k * 512);
                    CPC(); CPW1();
                } else CPW0();
                BARB();
            }
            const float* eb = e_b[c & 1];
            const int slo = max(mid, c * CH);
            #pragma unroll 4
            for (; s >= slo; --s) {
                const float* pp = &p_b[(s + 1) & 1][0];
                float u  = __expf(eb[(s - c * CH) * LAB + j]);
                float p0 = pp[0];
                int   e0 = ((__float_as_int(p0) >> 23) & 255) - 127;
                float sc = __int_as_float((127 - e0) << 23);
                Mi += e0;
                float us = (s == mid) ? sc : u * sc;   // s==mid: store E*z (no u; p_mid has it)
                const ulonglong2* pv =
                    reinterpret_cast<const ulonglong2*>(pp + g * 36);
                DOT_BODY(pv, q, v0.x);
                if (g == 0) p_b[s & 1][idx] = q * us;
                BARB();
            }
        }
        if (ltid == 0) mib_sh = Mi;                    // single writer
    }

    // ===================== COMBINE =====================
    __syncthreads();

    // dot of chain endpoints (both at parity mid&1)
    float vt = 0.0f;
    if (tid < 64) {
        int ii = (tid < 32) ? tid : tid + 4;
        vt = p_f[mid & 1][ii] * p_b[mid & 1][ii];
    }
    #pragma unroll
    for (int m = 16; m; m >>= 1)
        vt += __shfl_xor_sync(0xffffffffu, vt, m);
    if (tid == 0)  du[0] = vt;
    if (tid == 32) du[1] = vt;

    // labeled score: strided gather-sum (all 256 threads)
    float lsum = 0.0f;
    const int* tagb = tags + b * SEQ;
    for (int t2 = 1 + tid; t2 < len; t2 += 256) {
        int tg = tagb[t2], tp = tagb[t2 - 1];
        lsum += T[tp * LAB + tg] + encb[(size_t)t2 * LAB + tg];
    }
    #pragma unroll
    for (int m = 16; m; m >>= 1)
        lsum += __shfl_xor_sync(0xffffffffu, lsum, m);
    if ((tid & 31) == 0) lred[tid >> 5] = lsum;
    __syncthreads();

    if (tid == 0) {
        float ssum = du[0] + du[1];
        out[b] = (float)((double)(mif_sh + mib_sh) * 0.6931471805599453
                         + (double)logf(ssum));
        float ltot = 0.0f;
        #pragma unroll
        for (int k = 0; k < 8; ++k) ltot += lred[k];
        int t0g = tagb[0];
        int eg  = tagb[len - 1];
        out[BATCH + b] = ltot + T[START_ * LAB + t0g] + encb[t0g]
                       + T[eg * LAB + STOP_];
    }
}

extern "C" void kernel_launch(void* const* d_in, const int* in_sizes, int n_in,
                              void* d_out, int out_size)
{
    const float* enc  = (const float*)d_in[0];   // encoder_scores [32,512,64]
    const float* T    = (const float*)d_in[1];   // transition [64,64]
    const int*   lens = (const int*)  d_in[2];   // word_seq_lens [32]
    const int*   tags = (const int*)  d_in[3];   // tags [32,512]
    // d_in[4] = mask — recomputed from lens, unused
    float* out = (float*)d_out;                  // [64]: unlabeled(32) ++ labeled(32)

    crf_fwd_kernel<<<BATCH, 256>>>(enc, T, lens, tags, out);
}

// round 8
// speedup vs baseline: 2.2877x; 1.1837x over previous
#include <cuda_runtime.h>
#include <cstdint>

#define BATCH  32
#define SEQ    512
#define LAB    64
#define START_ 61
#define STOP_  62
#define CH     32          // enc chunk rows per cp.async stage

#define FMA2(d,a,b,c)  asm("fma.rn.f32x2 %0, %1, %2, %3;" : "=l"(d) : "l"(a), "l"(b), "l"(c))
#define ADD2(d,a,b)    asm("add.rn.f32x2 %0, %1, %2;"     : "=l"(d) : "l"(a), "l"(b))
#define PACK2(d,lo,hi) asm("mov.b64 %0, {%1, %2};"        : "=l"(d) : "f"(lo), "f"(hi))
#define UNPACK2(lo,hi,s) asm("mov.b64 {%0, %1}, %2;"      : "=f"(lo), "=f"(hi) : "l"(s))
#define CPA(dst,src) asm volatile("cp.async.cg.shared.global [%0], [%1], 16;\n" :: "r"(dst), "l"(src))
#define CPC() asm volatile("cp.async.commit_group;\n")
#define CPW1() asm volatile("cp.async.wait_group 1;\n")
#define CPW0() asm volatile("cp.async.wait_group 0;\n")

// one 64-wide half-dot: 8 LDS.128 + 16 FMA2 + tree + xor-1 shfl merge
#define DOT_BODY(PV, Q)                                                   \
    ulonglong2 v0 = (PV)[0], v1 = (PV)[1], v2 = (PV)[2], v3 = (PV)[3];    \
    ulonglong2 v4 = (PV)[4], v5 = (PV)[5], v6 = (PV)[6], v7 = (PV)[7];    \
    unsigned long long a0 = 0, a1 = 0, a2 = 0, a3 = 0;                    \
    FMA2(a0, v0.x, E2[ 0], a0); FMA2(a1, v0.y, E2[ 1], a1);               \
    FMA2(a2, v1.x, E2[ 2], a2); FMA2(a3, v1.y, E2[ 3], a3);               \
    FMA2(a0, v2.x, E2[ 4], a0); FMA2(a1, v2.y, E2[ 5], a1);               \
    FMA2(a2, v3.x, E2[ 6], a2); FMA2(a3, v3.y, E2[ 7], a3);               \
    FMA2(a0, v4.x, E2[ 8], a0); FMA2(a1, v4.y, E2[ 9], a1);               \
    FMA2(a2, v5.x, E2[10], a2); FMA2(a3, v5.y, E2[11], a3);               \
    FMA2(a0, v6.x, E2[12], a0); FMA2(a1, v6.y, E2[13], a1);               \
    FMA2(a2, v7.x, E2[14], a2); FMA2(a3, v7.y, E2[15], a3);               \
    unsigned long long s01, s23, sT;                                      \
    ADD2(s01, a0, a1); ADD2(s23, a2, a3); ADD2(sT, s01, s23);             \
    float qlo, qhi; UNPACK2(qlo, qhi, sT);                                \
    float Q = qlo + qhi;                                                  \
    Q += __shfl_xor_sync(0xffffffffu, Q, 1)

// inter-kernel scratch (static device globals — no allocation)
__device__ float g_vf[BATCH][LAB];
__device__ float g_vb[BATCH][LAB];
__device__ int   g_mi[2 * BATCH];

__global__ __launch_bounds__(128, 1)
void crf_chain_kernel(const float* __restrict__ enc,   // [B,S,L]
                      const float* __restrict__ T,     // [L,L]
                      const int*   __restrict__ lens)  // [B]
{
    __shared__ __align__(16) float e_sh[2][CH * LAB];  // enc chunk double buffer
    __shared__ __align__(16) float p_sh[2][72];        // state (scaled), padded halves

    const int b    = blockIdx.x >> 1;
    const int dir  = blockIdx.x & 1;                   // 0 = forward, 1 = backward
    const int tid  = threadIdx.x;
    const int len  = lens[b];
    const int mid  = (len - 1) >> 1;
    const float* encb = enc + (size_t)b * SEQ * LAB;

    const int j   = tid >> 1;
    const int g   = tid & 1;
    const int idx = (j < 32) ? j : j + 4;

    if (dir == 0) {
        // ============ FORWARD: p_t = D_{u_t} E^T p_{t-1}, t = 1..mid ============
        #pragma unroll
        for (int c = 0; c < 2; ++c) {
            const float* src = encb + c * CH * LAB + tid * 4;
            uint32_t dst = (uint32_t)__cvta_generic_to_shared(&e_sh[c][tid * 4]);
            #pragma unroll
            for (int k = 0; k < 4; ++k) CPA(dst + k * 2048, src + k * 512);
            CPC();
        }

        unsigned long long E2[16];                     // E column j, rows [g*32,+32)
        #pragma unroll
        for (int k = 0; k < 16; ++k) {
            float lo = expf(T[(g * 32 + 2 * k)     * LAB + j]);
            float hi = expf(T[(g * 32 + 2 * k + 1) * LAB + j]);
            PACK2(E2[k], lo, hi);
        }

        CPW1();
        __syncthreads();
        if (g == 0) p_sh[0][idx] = expf(T[START_ * LAB + j] + e_sh[0][j]);
        int Mi = 0;
        __syncthreads();

        const int nch = (mid >> 5) + 1;
        int t = 1;
        for (int c = 0; c < nch; ++c) {
            if (c >= 1) {
                if (c + 1 < nch) {
                    const float* src = encb + (c + 1) * CH * LAB + tid * 4;
                    uint32_t dst = (uint32_t)__cvta_generic_to_shared(
                                       &e_sh[(c + 1) & 1][tid * 4]);
                    #pragma unroll
                    for (int k = 0; k < 4; ++k) CPA(dst + k * 2048, src + k * 512);
                    CPC(); CPW1();
                } else CPW0();
                __syncthreads();
            }
            const float* eb = e_sh[c & 1];
            const int tt0   = t - c * CH;
            const int ttend = min(CH, mid + 1 - c * CH);
            #pragma unroll 4
            for (int tt = tt0; tt < ttend; ++tt, ++t) {
                const float* pp = &p_sh[(t - 1) & 1][0];
                float u  = __expf(eb[tt * LAB + j]);
                float p0 = pp[0];                              // broadcast LDS
                int   e0 = ((__float_as_int(p0) >> 23) & 255) - 127;
                float sc = __int_as_float((127 - e0) << 23);   // exact 2^-e0
                Mi += e0;
                float us = u * sc;
                const ulonglong2* pv =
                    reinterpret_cast<const ulonglong2*>(pp + g * 36);
                DOT_BODY(pv, q);
                if (g == 0) p_sh[t & 1][idx] = q * us;
                __syncthreads();
            }
        }
        if (g == 0) g_vf[b][j] = p_sh[mid & 1][idx];
        if (tid == 0) g_mi[b] = Mi;
    } else {
        // ============ BACKWARD: z_s = D_{u_s} E z_{s+1}, s = len-2..mid ============
        const int chi = (len - 2) >> 5;
        const int clo = mid >> 5;
        {
            const float* src = encb + chi * CH * LAB + tid * 4;
            uint32_t dst = (uint32_t)__cvta_generic_to_shared(&e_sh[chi & 1][tid * 4]);
            #pragma unroll
            for (int k = 0; k < 4; ++k) CPA(dst + k * 2048, src + k * 512);
            CPC();
        }
        if (chi - 1 >= clo) {
            const float* src = encb + (chi - 1) * CH * LAB + tid * 4;
            uint32_t dst = (uint32_t)__cvta_generic_to_shared(&e_sh[(chi - 1) & 1][tid * 4]);
            #pragma unroll
            for (int k = 0; k < 4; ++k) CPA(dst + k * 2048, src + k * 512);
            CPC();
        }

        unsigned long long E2[16];                     // E row j, cols [g*32,+32)
        #pragma unroll
        for (int k = 0; k < 16; ++k) {
            float lo = expf(T[j * LAB + g * 32 + 2 * k]);
            float hi = expf(T[j * LAB + g * 32 + 2 * k + 1]);
            PACK2(E2[k], lo, hi);
        }

        // z_{len-1}[i] = exp(T[i][STOP]) * exp(enc[len-1][i])
        if (g == 0)
            p_sh[(len - 1) & 1][idx] =
                expf(T[j * LAB + STOP_]) * __expf(encb[(size_t)(len - 1) * LAB + j]);
        int Mi = 0;
        if (chi - 1 >= clo) CPW1(); else CPW0();
        __syncthreads();

        int s = len - 2;
        for (int c = chi; c >= clo; --c) {
            if (c < chi) {
                if (c - 1 >= clo) {
                    const float* src = encb + (c - 1) * CH * LAB + tid * 4;
                    uint32_t dst = (uint32_t)__cvta_generic_to_shared(
                                       &e_sh[(c - 1) & 1][tid * 4]);
                    #pragma unroll
                    for (int k = 0; k < 4; ++k) CPA(dst + k * 2048, src + k * 512);
                    CPC(); CPW1();
                } else CPW0();
                __syncthreads();
            }
            const float* eb = e_sh[c & 1];
            const int slo = max(mid, c * CH);
            #pragma unroll 4
            for (; s >= slo; --s) {
                const float* pp = &p_sh[(s + 1) & 1][0];
                float u  = __expf(eb[(s - c * CH) * LAB + j]);
                float p0 = pp[0];
                int   e0 = ((__float_as_int(p0) >> 23) & 255) - 127;
                float sc = __int_as_float((127 - e0) << 23);
                Mi += e0;
                float us = (s == mid) ? sc : u * sc;   // s==mid: E*z only (p_f has u_mid)
                const ulonglong2* pv =
                    reinterpret_cast<const ulonglong2*>(pp + g * 36);
                DOT_BODY(pv, q);
                if (g == 0) p_sh[s & 1][idx] = q * us;
                __syncthreads();
            }
        }
        if (g == 0) g_vb[b][j] = p_sh[mid & 1][idx];
        if (tid == 0) g_mi[BATCH + b] = Mi;
    }
}

__global__ __launch_bounds__(128, 1)
void crf_combine_kernel(const float* __restrict__ enc,
                        const float* __restrict__ T,
                        const int*   __restrict__ lens,
                        const int*   __restrict__ tags,
                        float*       __restrict__ out)
{
    __shared__ float du[2];
    __shared__ float lred[4];

    const int b   = blockIdx.x;
    const int tid = threadIdx.x;
    const int len = lens[b];
    const float* encb = enc + (size_t)b * SEQ * LAB;
    const int* tagb = tags + b * SEQ;

    // unlabeled: dot of chain endpoints
    float vt = 0.0f;
    if (tid < LAB) vt = g_vf[b][tid] * g_vb[b][tid];
    #pragma unroll
    for (int m = 16; m; m >>= 1)
        vt += __shfl_xor_sync(0xffffffffu, vt, m);
    if (tid == 0)  du[0] = vt;
    if (tid == 32) du[1] = vt;

    // labeled: strided gather-sum
    float lsum = 0.0f;
    for (int t = 1 + tid; t < len; t += 128) {
        int tg = tagb[t], tp = tagb[t - 1];
        lsum += T[tp * LAB + tg] + encb[(size_t)t * LAB + tg];
    }
    #pragma unroll
    for (int m = 16; m; m >>= 1)
        lsum += __shfl_xor_sync(0xffffffffu, lsum, m);
    if ((tid & 31) == 0) lred[tid >> 5] = lsum;
    __syncthreads();

    if (tid == 0) {
        float ssum = du[0] + du[1];
        out[b] = (float)((double)(g_mi[b] + g_mi[BATCH + b]) * 0.6931471805599453
                         + (double)logf(ssum));
        int t0g = tagb[0];
        int eg  = tagb[len - 1];
        out[BATCH + b] = lred[0] + lred[1] + lred[2] + lred[3]
                       + T[START_ * LAB + t0g] + encb[t0g]
                       + T[eg * LAB + STOP_];
    }
}

extern "C" void kernel_launch(void* const* d_in, const int* in_sizes, int n_in,
                              void* d_out, int out_size)
{
    const float* enc  = (const float*)d_in[0];   // encoder_scores [32,512,64]
    const float* T    = (const float*)d_in[1];   // transition [64,64]
    const int*   lens = (const int*)  d_in[2];   // word_seq_lens [32]
    const int*   tags = (const int*)  d_in[3];   // tags [32,512]
    float* out = (float*)d_out;                  // [64]: unlabeled(32) ++ labeled(32)

    crf_chain_kernel<<<2 * BATCH, 128>>>(enc, T, lens);
    crf_combine_kernel<<<BATCH, 128>>>(enc, T, lens, tags, out);
}

// round 9
// speedup vs baseline: 2.3913x; 1.0453x over previous
#include <cuda_runtime.h>
#include <cstdint>

#define BATCH  32
#define SEQ    512
#define LAB    64
#define START_ 61
#define STOP_  62
#define CH     32          // enc chunk rows per cp.async stage

#define FMA2(d,a,b,c)  asm("fma.rn.f32x2 %0, %1, %2, %3;" : "=l"(d) : "l"(a), "l"(b), "l"(c))
#define ADD2(d,a,b)    asm("add.rn.f32x2 %0, %1, %2;"     : "=l"(d) : "l"(a), "l"(b))
#define PACK2(d,lo,hi) asm("mov.b64 %0, {%1, %2};"        : "=l"(d) : "f"(lo), "f"(hi))
#define UNPACK2(lo,hi,s) asm("mov.b64 {%0, %1}, %2;"      : "=f"(lo), "=f"(hi) : "l"(s))
#define CPA(dst,src) asm volatile("cp.async.cg.shared.global [%0], [%1], 16;\n" :: "r"(dst), "l"(src))
#define CPC() asm volatile("cp.async.commit_group;\n")
#define CPW1() asm volatile("cp.async.wait_group 1;\n")
#define CPW0() asm volatile("cp.async.wait_group 0;\n")

// one 64-wide half-dot: 8 LDS.128 + 16 FMA2 + tree + xor-1 shfl merge
#define DOT_BODY(PV, Q)                                                   \
    ulonglong2 v0 = (PV)[0], v1 = (PV)[1], v2 = (PV)[2], v3 = (PV)[3];    \
    ulonglong2 v4 = (PV)[4], v5 = (PV)[5], v6 = (PV)[6], v7 = (PV)[7];    \
    unsigned long long a0 = 0, a1 = 0, a2 = 0, a3 = 0;                    \
    FMA2(a0, v0.x, E2[ 0], a0); FMA2(a1, v0.y, E2[ 1], a1);               \
    FMA2(a2, v1.x, E2[ 2], a2); FMA2(a3, v1.y, E2[ 3], a3);               \
    FMA2(a0, v2.x, E2[ 4], a0); FMA2(a1, v2.y, E2[ 5], a1);               \
    FMA2(a2, v3.x, E2[ 6], a2); FMA2(a3, v3.y, E2[ 7], a3);               \
    FMA2(a0, v4.x, E2[ 8], a0); FMA2(a1, v4.y, E2[ 9], a1);               \
    FMA2(a2, v5.x, E2[10], a2); FMA2(a3, v5.y, E2[11], a3);               \
    FMA2(a0, v6.x, E2[12], a0); FMA2(a1, v6.y, E2[13], a1);               \
    FMA2(a2, v7.x, E2[14], a2); FMA2(a3, v7.y, E2[15], a3);               \
    unsigned long long s01, s23, sT;                                      \
    ADD2(s01, a0, a1); ADD2(s23, a2, a3); ADD2(sT, s01, s23);             \
    float qlo, qhi; UNPACK2(qlo, qhi, sT);                                \
    float Q = qlo + qhi;                                                  \
    Q += __shfl_xor_sync(0xffffffffu, Q, 1)

// inter-block scratch (static device globals — no allocation)
__device__ float g_vf[BATCH][LAB];
__device__ float g_vb[BATCH][LAB];
__device__ int   g_mi[2 * BATCH];
__device__ int   g_cnt[BATCH];     // never reset; +2 per launch; parity selects combiner

__global__ __launch_bounds__(128, 1)
void crf_fused_kernel(const float* __restrict__ enc,   // [B,S,L]
                      const float* __restrict__ T,     // [L,L]
                      const int*   __restrict__ lens,  // [B]
                      const int*   __restrict__ tags,  // [B,S]
                      float*       __restrict__ out)   // [2*B]
{
    const int tid = threadIdx.x;

    // ================= LABELED blocks: 64..95 =================
    if (blockIdx.x >= 2 * BATCH) {
        const int b   = blockIdx.x - 2 * BATCH;
        const int len = lens[b];
        const float* encb = enc + (size_t)b * SEQ * LAB;
        const int*   tagb = tags + b * SEQ;
        __shared__ float lred[4];

        float lsum = 0.0f;
        for (int t = 1 + tid; t < len; t += 128) {
            int tg = tagb[t], tp = tagb[t - 1];
            lsum += T[tp * LAB + tg] + encb[(size_t)t * LAB + tg];
        }
        #pragma unroll
        for (int m = 16; m; m >>= 1)
            lsum += __shfl_xor_sync(0xffffffffu, lsum, m);
        if ((tid & 31) == 0) lred[tid >> 5] = lsum;
        __syncthreads();
        if (tid == 0) {
            int t0g = tagb[0];
            int eg  = tagb[len - 1];
            out[BATCH + b] = lred[0] + lred[1] + lred[2] + lred[3]
                           + T[START_ * LAB + t0g] + encb[t0g]
                           + T[eg * LAB + STOP_];
        }
        return;
    }

    // ================= CHAIN blocks: 0..63 =================
    __shared__ __align__(16) float e_sh[2][CH * LAB];
    __shared__ __align__(16) float p_sh[2][72];        // state (scaled), padded halves
    __shared__ int win_sh;

    const int b    = blockIdx.x >> 1;
    const int dir  = blockIdx.x & 1;                   // 0 = forward, 1 = backward
    const int len  = lens[b];
    const int mid  = (len - 1) >> 1;
    const float* encb = enc + (size_t)b * SEQ * LAB;

    const int j   = tid >> 1;
    const int g   = tid & 1;
    const int idx = (j < 32) ? j : j + 4;

    if (dir == 0) {
        // ---- FORWARD: p_t = D_{u_t} E^T p_{t-1}, t = 1..mid ----
        #pragma unroll
        for (int c = 0; c < 2; ++c) {
            const float* src = encb + c * CH * LAB + tid * 4;
            uint32_t dst = (uint32_t)__cvta_generic_to_shared(&e_sh[c][tid * 4]);
            #pragma unroll
            for (int k = 0; k < 4; ++k) CPA(dst + k * 2048, src + k * 512);
            CPC();
        }

        unsigned long long E2[16];                     // E column j, rows [g*32,+32)
        #pragma unroll
        for (int k = 0; k < 16; ++k) {
            float lo = expf(T[(g * 32 + 2 * k)     * LAB + j]);
            float hi = expf(T[(g * 32 + 2 * k + 1) * LAB + j]);
            PACK2(E2[k], lo, hi);
        }

        CPW1();
        __syncthreads();
        if (g == 0) p_sh[0][idx] = expf(T[START_ * LAB + j] + e_sh[0][j]);
        int Mi = 0;
        __syncthreads();

        const int nch = (mid >> 5) + 1;
        int t = 1;
        for (int c = 0; c < nch; ++c) {
            if (c >= 1) {
                if (c + 1 < nch) {
                    const float* src = encb + (c + 1) * CH * LAB + tid * 4;
                    uint32_t dst = (uint32_t)__cvta_generic_to_shared(
                                       &e_sh[(c + 1) & 1][tid * 4]);
                    #pragma unroll
                    for (int k = 0; k < 4; ++k) CPA(dst + k * 2048, src + k * 512);
                    CPC(); CPW1();
                } else CPW0();
                __syncthreads();
            }
            const float* eb = e_sh[c & 1];
            const int tt0   = t - c * CH;
            const int ttend = min(CH, mid + 1 - c * CH);
            #pragma unroll 4
            for (int tt = tt0; tt < ttend; ++tt, ++t) {
                const float* pp = &p_sh[(t - 1) & 1][0];
                float u  = __expf(eb[tt * LAB + j]);
                float p0 = pp[0];
                int   e0 = ((__float_as_int(p0) >> 23) & 255) - 127;
                float sc = __int_as_float((127 - e0) << 23);
                Mi += e0;
                float us = u * sc;
                const ulonglong2* pv =
                    reinterpret_cast<const ulonglong2*>(pp + g * 36);
                DOT_BODY(pv, q);
                if (g == 0) p_sh[t & 1][idx] = q * us;
                __syncthreads();
            }
        }
        if (g == 0) g_vf[b][j] = p_sh[mid & 1][idx];
        if (tid == 0) g_mi[b] = Mi;
    } else {
        // ---- BACKWARD: z_s = D_{u_s} E z_{s+1}, s = len-2..mid ----
        const int chi = (len - 2) >> 5;
        const int clo = mid >> 5;
        {
            const float* src = encb + chi * CH * LAB + tid * 4;
            uint32_t dst = (uint32_t)__cvta_generic_to_shared(&e_sh[chi & 1][tid * 4]);
            #pragma unroll
            for (int k = 0; k < 4; ++k) CPA(dst + k * 2048, src + k * 512);
            CPC();
        }
        if (chi - 1 >= clo) {
            const float* src = encb + (chi - 1) * CH * LAB + tid * 4;
            uint32_t dst = (uint32_t)__cvta_generic_to_shared(&e_sh[(chi - 1) & 1][tid * 4]);
            #pragma unroll
            for (int k = 0; k < 4; ++k) CPA(dst + k * 2048, src + k * 512);
            CPC();
        }

        unsigned long long E2[16];                     // E row j, cols [g*32,+32)
        #pragma unroll
        for (int k = 0; k < 16; ++k) {
            float lo = expf(T[j * LAB + g * 32 + 2 * k]);
            float hi = expf(T[j * LAB + g * 32 + 2 * k + 1]);
            PACK2(E2[k], lo, hi);
        }

        if (g == 0)
            p_sh[(len - 1) & 1][idx] =
                expf(T[j * LAB + STOP_]) * __expf(encb[(size_t)(len - 1) * LAB + j]);
        int Mi = 0;
        if (chi - 1 >= clo) CPW1(); else CPW0();
        __syncthreads();

        int s = len - 2;
        for (int c = chi; c >= clo; --c) {
            if (c < chi) {
                if (c - 1 >= clo) {
                    const float* src = encb + (c - 1) * CH * LAB + tid * 4;
                    uint32_t dst = (uint32_t)__cvta_generic_to_shared(
                                       &e_sh[(c - 1) & 1][tid * 4]);
                    #pragma unroll
                    for (int k = 0; k < 4; ++k) CPA(dst + k * 2048, src + k * 512);
                    CPC(); CPW1();
                } else CPW0();
                __syncthreads();
            }
            const float* eb = e_sh[c & 1];
            const int slo = max(mid, c * CH);
            #pragma unroll 4
            for (; s >= slo; --s) {
                const float* pp = &p_sh[(s + 1) & 1][0];
                float u  = __expf(eb[(s - c * CH) * LAB + j]);
                float p0 = pp[0];
                int   e0 = ((__float_as_int(p0) >> 23) & 255) - 127;
                float sc = __int_as_float((127 - e0) << 23);
                Mi += e0;
                float us = (s == mid) ? sc : u * sc;   // s==mid: E*z only (p_f has u_mid)
                const ulonglong2* pv =
                    reinterpret_cast<const ulonglong2*>(pp + g * 36);
                DOT_BODY(pv, q);
                if (g == 0) p_sh[s & 1][idx] = q * us;
                __syncthreads();
            }
        }
        if (g == 0) g_vb[b][j] = p_sh[mid & 1][idx];
        if (tid == 0) g_mi[BATCH + b] = Mi;
    }

    // ---- last-arriver combine (unlabeled output) ----
    __threadfence();
    __syncthreads();
    if (tid == 0) {
        int old = atomicAdd(&g_cnt[b], 1);
        win_sh = (old & 1);                // second of the pair this launch
    }
    __syncthreads();
    if (win_sh) {
        __shared__ float du[2];
        float vt = 0.0f;
        if (tid < LAB)
            vt = __ldcg(&g_vf[b][tid]) * __ldcg(&g_vb[b][tid]);
        #pragma unroll
        for (int m = 16; m; m >>= 1)
            vt += __shfl_xor_sync(0xffffffffu, vt, m);
        if (tid == 0)  du[0] = vt;
        if (tid == 32) du[1] = vt;
        __syncthreads();
        if (tid == 0) {
            float ssum = du[0] + du[1];
            int mi_tot = __ldcg(&g_mi[b]) + __ldcg(&g_mi[BATCH + b]);
            out[b] = (float)((double)mi_tot * 0.6931471805599453
                             + (double)logf(ssum));
        }
    }
}

extern "C" void kernel_launch(void* const* d_in, const int* in_sizes, int n_in,
                              void* d_out, int out_size)
{
    const float* enc  = (const float*)d_in[0];   // encoder_scores [32,512,64]
    const float* T    = (const float*)d_in[1];   // transition [64,64]
    const int*   lens = (const int*)  d_in[2];   // word_seq_lens [32]
    const int*   tags = (const int*)  d_in[3];   // tags [32,512]
    float* out = (float*)d_out;                  // [64]: unlabeled(32) ++ labeled(32)

    crf_fused_kernel<<<3 * BATCH, 128>>>(enc, T, lens, tags, out);
}

// round 10
// speedup vs baseline: 3.1169x; 1.3034x over previous
#include <cuda_runtime.h>
#include <cstdint>

#define BATCH  32
#define SEQ    512
#define LAB    64
#define START_ 61
#define STOP_  62
#define CH     32

#define FMA2(d,a,b,c)  asm("fma.rn.f32x2 %0, %1, %2, %3;" : "=l"(d) : "l"(a), "l"(b), "l"(c))
#define ADD2(d,a,b)    asm("add.rn.f32x2 %0, %1, %2;"     : "=l"(d) : "l"(a), "l"(b))
#define PACK2(d,lo,hi) asm("mov.b64 %0, {%1, %2};"        : "=l"(d) : "f"(lo), "f"(hi))
#define UNPACK2(lo,hi,s) asm("mov.b64 {%0, %1}, %2;"      : "=f"(lo), "=f"(hi) : "l"(s))
#define CPA(dst,src) asm volatile("cp.async.cg.shared.global [%0], [%1], 16;\n" :: "r"(dst), "l"(src))
#define CPC() asm volatile("cp.async.commit_group;\n")
#define CPW1() asm volatile("cp.async.wait_group 1;\n")
#define CPW0() asm volatile("cp.async.wait_group 0;\n")

#define PREFETCH(cc) do {                                                       \
    const float* _src = encb + (size_t)(cc) * CH * LAB + tid * 4;               \
    uint32_t _dst = (uint32_t)__cvta_generic_to_shared(&e_sh[(cc) & 1][tid*4]); \
    CPA(_dst,        _src);        CPA(_dst + 2048, _src + 512);                \
    CPA(_dst + 4096, _src + 1024); CPA(_dst + 6144, _src + 1536);               \
    CPC();                                                                      \
} while (0)

// one 64-wide half-dot: 8 LDS.128 + 16 FMA2 + tree + xor-1 shfl merge
#define DOT_BODY(PV, Q)                                                   \
    ulonglong2 v0 = (PV)[0], v1 = (PV)[1], v2 = (PV)[2], v3 = (PV)[3];    \
    ulonglong2 v4 = (PV)[4], v5 = (PV)[5], v6 = (PV)[6], v7 = (PV)[7];    \
    unsigned long long a0 = 0, a1 = 0, a2 = 0, a3 = 0;                    \
    FMA2(a0, v0.x, E2[ 0], a0); FMA2(a1, v0.y, E2[ 1], a1);               \
    FMA2(a2, v1.x, E2[ 2], a2); FMA2(a3, v1.y, E2[ 3], a3);               \
    FMA2(a0, v2.x, E2[ 4], a0); FMA2(a1, v2.y, E2[ 5], a1);               \
    FMA2(a2, v3.x, E2[ 6], a2); FMA2(a3, v3.y, E2[ 7], a3);               \
    FMA2(a0, v4.x, E2[ 8], a0); FMA2(a1, v4.y, E2[ 9], a1);               \
    FMA2(a2, v5.x, E2[10], a2); FMA2(a3, v5.y, E2[11], a3);               \
    FMA2(a0, v6.x, E2[12], a0); FMA2(a1, v6.y, E2[13], a1);               \
    FMA2(a2, v7.x, E2[14], a2); FMA2(a3, v7.y, E2[15], a3);               \
    unsigned long long s01, s23, sT;                                      \
    ADD2(s01, a0, a1); ADD2(s23, a2, a3); ADD2(sT, s01, s23);             \
    float qlo, qhi; UNPACK2(qlo, qhi, sT);                                \
    float Q = qlo + qhi;                                                  \
    Q += __shfl_xor_sync(0xffffffffu, Q, 1)

// inter-block scratch (static device globals — no allocation)
// chains: 0 = fwd main (x), 1 = fwd probe (f), 2 = bwd probe (g), 3 = bwd main (y)
__device__ float g_v[4][BATCH][LAB];
__device__ int   g_mi4[4][BATCH];
__device__ int   g_cnt[BATCH];     // never reset; +4 per launch; (old&3)==3 -> combiner

__global__ __launch_bounds__(128, 1)
void crf_fused_kernel(const float* __restrict__ enc,   // [B,S,L]
                      const float* __restrict__ T,     // [L,L]
                      const int*   __restrict__ lens,  // [B]
                      const int*   __restrict__ tags,  // [B,S]
                      float*       __restrict__ out)   // [2*B]
{
    const int tid = threadIdx.x;

    // ================= LABELED blocks: 128..159 =================
    if (blockIdx.x >= 4 * BATCH) {
        const int b   = blockIdx.x - 4 * BATCH;
        const int len = lens[b];
        const float* encb = enc + (size_t)b * SEQ * LAB;
        const int*   tagb = tags + b * SEQ;
        __shared__ float lred[4];

        float lsum = 0.0f;
        for (int t = 1 + tid; t < len; t += 128) {
            int tg = tagb[t], tp = tagb[t - 1];
            lsum += T[tp * LAB + tg] + encb[(size_t)t * LAB + tg];
        }
        #pragma unroll
        for (int m = 16; m; m >>= 1)
            lsum += __shfl_xor_sync(0xffffffffu, lsum, m);
        if ((tid & 31) == 0) lred[tid >> 5] = lsum;
        __syncthreads();
        if (tid == 0) {
            int t0g = tagb[0];
            int eg  = tagb[len - 1];
            out[BATCH + b] = lred[0] + lred[1] + lred[2] + lred[3]
                           + T[START_ * LAB + t0g] + encb[t0g]
                           + T[eg * LAB + STOP_];
        }
        return;
    }

    // ================= CHAIN blocks: 0..127 =================
    __shared__ __align__(16) float e_sh[2][CH * LAB];
    __shared__ __align__(16) float p_sh[2][72];        // state (scaled), padded halves
    __shared__ int win_sh;
    __shared__ float du[6];

    const int b   = blockIdx.x >> 2;
    const int k   = blockIdx.x & 3;
    const int len = lens[b];
    const int n   = len - 1;
    const int sa  = n / 3;             // split point 1 (1 <= sa < sb <= len-2)
    const int sb  = (2 * n) / 3;       // split point 2
    const float* encb = enc + (size_t)b * SEQ * LAB;

    const int j   = tid >> 1;
    const int g   = tid & 1;
    const int idx = (j < 32) ? j : j + 4;

    int Mi = 0;
    int par_out;

    if (k <= 1) {
        // ---- FORWARD chains: p_t = D_{u_t} E^T p_{t-1} ----
        // k=0: t = 1..sa,  init p_0 = exp(T[START,:]+enc[0,:])   -> x
        // k=1: t = sa+1..sb, init p_sa = ones (probe)            -> f = P2*1
        const int t0 = (k == 0) ? 1 : sa + 1;
        const int t1 = (k == 0) ? sa : sb;

        unsigned long long E2[16];                     // E column j, rows [g*32,+32)
        #pragma unroll
        for (int kk = 0; kk < 16; ++kk) {
            float lo = expf(T[(g * 32 + 2 * kk)     * LAB + j]);
            float hi = expf(T[(g * 32 + 2 * kk + 1) * LAB + j]);
            PACK2(E2[kk], lo, hi);
        }

        const int c0 = t0 >> 5, c1 = t1 >> 5;
        PREFETCH(c0);
        if (c0 < c1) { PREFETCH(c0 + 1); CPW1(); } else CPW0();
        __syncthreads();
        if (g == 0) {
            if (k == 0) p_sh[0][idx] = expf(T[START_ * LAB + j] + e_sh[0][j]);
            else        p_sh[(t0 - 1) & 1][idx] = 1.0f;
        }
        __syncthreads();

        int t = t0;
        for (int c = c0; c <= c1; ++c) {
            if (c > c0) {
                if (c < c1) { PREFETCH(c + 1); CPW1(); } else CPW0();
                __syncthreads();
            }
            const float* eb = e_sh[c & 1];
            const int ttend = min((c + 1) * CH - 1, t1);
            #pragma unroll 4
            for (; t <= ttend; ++t) {
                const float* pp = &p_sh[(t - 1) & 1][0];
                float u  = __expf(eb[(t - c * CH) * LAB + j]);
                float p0 = pp[0];
                int   e0 = ((__float_as_int(p0) >> 23) & 255) - 127;
                float sc = __int_as_float((127 - e0) << 23);
                Mi += e0;
                float us = u * sc;
                const ulonglong2* pv =
                    reinterpret_cast<const ulonglong2*>(pp + g * 36);
                DOT_BODY(pv, q);
                if (g == 0) p_sh[t & 1][idx] = q * us;
                __syncthreads();
            }
        }
        par_out = t1 & 1;
    } else {
        // ---- BACKWARD chains: w_s = D_{u_s} E w_{s+1}; last step drops u ----
        // k=3: s = len-2..sb, init w_{len-1} = D_u exp(T[:,STOP]) -> y~ = E w_{sb+1}
        // k=2: s = sb-1..sa,  init w_sb = u_sb (probe = ones)     -> g = P2^T*1
        const int s1 = (k == 3) ? len - 2 : sb - 1;
        const int s0 = (k == 3) ? sb : sa;

        unsigned long long E2[16];                     // E row j, cols [g*32,+32)
        #pragma unroll
        for (int kk = 0; kk < 16; ++kk) {
            float lo = expf(T[j * LAB + g * 32 + 2 * kk]);
            float hi = expf(T[j * LAB + g * 32 + 2 * kk + 1]);
            PACK2(E2[kk], lo, hi);
        }

        const int chi = s1 >> 5, clo = s0 >> 5;
        PREFETCH(chi);
        if (chi > clo) PREFETCH(chi - 1);
        if (g == 0) {
            if (k == 3)
                p_sh[(len - 1) & 1][idx] =
                    expf(T[j * LAB + STOP_]) * __expf(encb[(size_t)(len - 1) * LAB + j]);
            else
                p_sh[(s1 + 1) & 1][idx] = __expf(encb[(size_t)(s1 + 1) * LAB + j]);
        }
        if (chi > clo) CPW1(); else CPW0();
        __syncthreads();

        int s = s1;
        for (int c = chi; c >= clo; --c) {
            if (c < chi) {
                if (c > clo) { PREFETCH(c - 1); CPW1(); } else CPW0();
                __syncthreads();
            }
            const float* eb = e_sh[c & 1];
            const int slo = max(s0, c * CH);
            #pragma unroll 4
            for (; s >= slo; --s) {
                const float* pp = &p_sh[(s + 1) & 1][0];
                float u  = __expf(eb[(s - c * CH) * LAB + j]);
                float p0 = pp[0];
                int   e0 = ((__float_as_int(p0) >> 23) & 255) - 127;
                float sc = __int_as_float((127 - e0) << 23);
                Mi += e0;
                float us = (s == s0) ? sc : u * sc;    // boundary: apply E only
                const ulonglong2* pv =
                    reinterpret_cast<const ulonglong2*>(pp + g * 36);
                DOT_BODY(pv, q);
                if (g == 0) p_sh[s & 1][idx] = q * us;
                __syncthreads();
            }
        }
        par_out = s0 & 1;
    }

    if (g == 0) g_v[k][b][j] = p_sh[par_out][idx];
    if (tid == 0) g_mi4[k][b] = Mi;

    // ---- last-arriver combine (unlabeled output) ----
    __threadfence();
    __syncthreads();
    if (tid == 0) {
        int old = atomicAdd(&g_cnt[b], 1);
        win_sh = ((old & 3) == 3);         // 4th of the quad this launch
    }
    __syncthreads();
    if (win_sh) {
        float d1 = 0.0f, d2 = 0.0f, d3 = 0.0f;
        if (tid < LAB) {
            float xv = __ldcg(&g_v[0][b][tid]);
            float fv = __ldcg(&g_v[1][b][tid]);
            float gv = __ldcg(&g_v[2][b][tid]);
            float yv = __ldcg(&g_v[3][b][tid]);
            d1 = yv * fv;                  // y~ . f
            d2 = gv * xv;                  // g  . x
            d3 = fv;                       // 1  . f
        }
        #pragma unroll
        for (int m = 16; m; m >>= 1) {
            d1 += __shfl_xor_sync(0xffffffffu, d1, m);
            d2 += __shfl_xor_sync(0xffffffffu, d2, m);
            d3 += __shfl_xor_sync(0xffffffffu, d3, m);
        }
        if (tid == 0)  { du[0] = d1; du[1] = d2; du[2] = d3; }
        if (tid == 32) { du[3] = d1; du[4] = d2; du[5] = d3; }
        __syncthreads();
        if (tid == 0) {
            float D1 = du[0] + du[3];
            float D2 = du[1] + du[4];
            float D3 = du[2] + du[5];
            int mtot = __ldcg(&g_mi4[0][b]) + __ldcg(&g_mi4[2][b])
                     + __ldcg(&g_mi4[3][b]);              // MiF cancels exactly
            out[b] = (float)((double)mtot * 0.6931471805599453
                             + (double)(logf(D1) + logf(D2) - logf(D3)));
        }
    }
}

extern "C" void kernel_launch(void* const* d_in, const int* in_sizes, int n_in,
                              void* d_out, int out_size)
{
    const float* enc  = (const float*)d_in[0];   // encoder_scores [32,512,64]
    const float* T    = (const float*)d_in[1];   // transition [64,64]
    const int*   lens = (const int*)  d_in[2];   // word_seq_lens [32]
    const int*   tags = (const int*)  d_in[3];   // tags [32,512]
    float* out = (float*)d_out;                  // [64]: unlabeled(32) ++ labeled(32)

    crf_fused_kernel<<<5 * BATCH, 128>>>(enc, T, lens, tags, out);
}

// round 11
// speedup vs baseline: 3.3673x; 1.0804x over previous
#include <cuda_runtime.h>
#include <cstdint>

#define BATCH  32
#define SEQ    512
#define LAB    64
#define START_ 61
#define STOP_  62
#define CH     32

#define FMA2(d,a,b,c)  asm("fma.rn.f32x2 %0, %1, %2, %3;" : "=l"(d) : "l"(a), "l"(b), "l"(c))
#define ADD2(d,a,b)    asm("add.rn.f32x2 %0, %1, %2;"     : "=l"(d) : "l"(a), "l"(b))
#define PACK2(d,lo,hi) asm("mov.b64 %0, {%1, %2};"        : "=l"(d) : "f"(lo), "f"(hi))
#define UNPACK2(lo,hi,s) asm("mov.b64 {%0, %1}, %2;"      : "=f"(lo), "=f"(hi) : "l"(s))
#define CPA(dst,src) asm volatile("cp.async.cg.shared.global [%0], [%1], 16;\n" :: "r"(dst), "l"(src))
#define CPC() asm volatile("cp.async.commit_group;\n")
#define CPW1() asm volatile("cp.async.wait_group 1;\n")
#define CPW0() asm volatile("cp.async.wait_group 0;\n")

#define PREFETCH(cc) do {                                                       \
    const float* _src = encb + (size_t)(cc) * CH * LAB + tid * 4;               \
    uint32_t _dst = (uint32_t)__cvta_generic_to_shared(&e_sh[(cc) & 1][tid*4]); \
    CPA(_dst,        _src);        CPA(_dst + 2048, _src + 512);                \
    CPA(_dst + 4096, _src + 1024); CPA(_dst + 6144, _src + 1536);               \
    CPC();                                                                      \
} while (0)

// one 64-wide half-dot: 8 LDS.128 + 16 FMA2 + tree + xor-1 shfl merge
#define DOT_BODY(PV, Q)                                                   \
    ulonglong2 v0 = (PV)[0], v1 = (PV)[1], v2 = (PV)[2], v3 = (PV)[3];    \
    ulonglong2 v4 = (PV)[4], v5 = (PV)[5], v6 = (PV)[6], v7 = (PV)[7];    \
    unsigned long long a0 = 0, a1 = 0, a2 = 0, a3 = 0;                    \
    FMA2(a0, v0.x, E2[ 0], a0); FMA2(a1, v0.y, E2[ 1], a1);               \
    FMA2(a2, v1.x, E2[ 2], a2); FMA2(a3, v1.y, E2[ 3], a3);               \
    FMA2(a0, v2.x, E2[ 4], a0); FMA2(a1, v2.y, E2[ 5], a1);               \
    FMA2(a2, v3.x, E2[ 6], a2); FMA2(a3, v3.y, E2[ 7], a3);               \
    FMA2(a0, v4.x, E2[ 8], a0); FMA2(a1, v4.y, E2[ 9], a1);               \
    FMA2(a2, v5.x, E2[10], a2); FMA2(a3, v5.y, E2[11], a3);               \
    FMA2(a0, v6.x, E2[12], a0); FMA2(a1, v6.y, E2[13], a1);               \
    FMA2(a2, v7.x, E2[14], a2); FMA2(a3, v7.y, E2[15], a3);               \
    unsigned long long s01, s23, sT;                                      \
    ADD2(s01, a0, a1); ADD2(s23, a2, a3); ADD2(sT, s01, s23);             \
    float qlo, qhi; UNPACK2(qlo, qhi, sT);                                \
    float Q = qlo + qhi;                                                  \
    Q += __shfl_xor_sync(0xffffffffu, Q, 1)

// chains per batch: 0=x(seg1) 1=f2 2=f3 3=f4 4=g2 5=g3 6=g4 7=y(seg5)
__device__ float g_v[8][BATCH][LAB];
__device__ int   g_mi8[8][BATCH];
__device__ int   g_cnt[BATCH];     // never reset; +8 per launch; (old&7)==7 -> combiner

__global__ __launch_bounds__(128, 1)
void crf_fused_kernel(const float* __restrict__ enc,   // [B,S,L]
                      const float* __restrict__ T,     // [L,L]
                      const int*   __restrict__ lens,  // [B]
                      const int*   __restrict__ tags,  // [B,S]
                      float*       __restrict__ out)   // [2*B]
{
    const int tid = threadIdx.x;

    // ================= LABELED blocks: 256..287 =================
    if (blockIdx.x >= 8 * BATCH) {
        const int b   = blockIdx.x - 8 * BATCH;
        const int len = lens[b];
        const float* encb = enc + (size_t)b * SEQ * LAB;
        const int*   tagb = tags + b * SEQ;
        __shared__ float lred[4];

        float lsum = 0.0f;
        for (int t = 1 + tid; t < len; t += 128) {
            int tg = tagb[t], tp = tagb[t - 1];
            lsum += T[tp * LAB + tg] + encb[(size_t)t * LAB + tg];
        }
        #pragma unroll
        for (int m = 16; m; m >>= 1)
            lsum += __shfl_xor_sync(0xffffffffu, lsum, m);
        if ((tid & 31) == 0) lred[tid >> 5] = lsum;
        __syncthreads();
        if (tid == 0) {
            int t0g = tagb[0];
            int eg  = tagb[len - 1];
            out[BATCH + b] = lred[0] + lred[1] + lred[2] + lred[3]
                           + T[START_ * LAB + t0g] + encb[t0g]
                           + T[eg * LAB + STOP_];
        }
        return;
    }

    // ================= CHAIN blocks: 0..255 =================
    __shared__ __align__(16) float e_sh[2][CH * LAB];
    __shared__ __align__(16) float p_sh[2][72];
    __shared__ int win_sh;
    __shared__ float du[14];

    const int b   = blockIdx.x >> 3;
    const int k   = blockIdx.x & 7;
    const int len = lens[b];
    const int n   = len - 1;
    // segment boundaries sB[i] = i*n/5
    int sB[6];
    #pragma unroll
    for (int i = 0; i <= 5; ++i) sB[i] = (i * n) / 5;
    const float* encb = enc + (size_t)b * SEQ * LAB;

    const int j   = tid >> 1;
    const int g   = tid & 1;
    const int idx = (j < 32) ? j : j + 4;

    int Mi = 0;
    int par_out;

    if (k <= 3) {
        // ---- FORWARD chains: p <- D_u E^T p over seg k+1 = (sB[k], sB[k+1]] ----
        const int t0 = sB[k] + 1;
        const int t1 = sB[k + 1];

        unsigned long long E2[16];                     // E column j, rows [g*32,+32)
        #pragma unroll
        for (int kk = 0; kk < 16; ++kk) {
            float lo = expf(T[(g * 32 + 2 * kk)     * LAB + j]);
            float hi = expf(T[(g * 32 + 2 * kk + 1) * LAB + j]);
            PACK2(E2[kk], lo, hi);
        }

        const int c0 = t0 >> 5, c1 = t1 >> 5;
        PREFETCH(c0);
        if (c0 < c1) { PREFETCH(c0 + 1); CPW1(); } else CPW0();
        __syncthreads();
        if (g == 0) {
            if (k == 0) p_sh[0][idx] = expf(T[START_ * LAB + j] + e_sh[0][j]);
            else        p_sh[(t0 - 1) & 1][idx] = 1.0f;   // probe: ones
        }
        __syncthreads();

        int t = t0;
        for (int c = c0; c <= c1; ++c) {
            if (c > c0) {
                if (c < c1) { PREFETCH(c + 1); CPW1(); } else CPW0();
                __syncthreads();
            }
            const float* eb = e_sh[c & 1];
            const int ttend = min((c + 1) * CH - 1, t1);
            #pragma unroll 4
            for (; t <= ttend; ++t) {
                const float* pp = &p_sh[(t - 1) & 1][0];
                float u  = __expf(eb[(t - c * CH) * LAB + j]);
                float p0 = pp[0];
                int   e0 = ((__float_as_int(p0) >> 23) & 255) - 127;
                float sc = __int_as_float((127 - e0) << 23);
                Mi += e0;
                float us = u * sc;
                const ulonglong2* pv =
                    reinterpret_cast<const ulonglong2*>(pp + g * 36);
                DOT_BODY(pv, q);
                if (g == 0) p_sh[t & 1][idx] = q * us;
                __syncthreads();
            }
        }
        par_out = t1 & 1;
    } else {
        // ---- BACKWARD chains: w <- D_u E w over seg sg = (sB[sg-1], sB[sg]] ----
        // k=4..6: probes g2..g4 (init ones*u). k=7: y (init c*u_n). Last step E-only.
        const int sg = k - 2;                          // 2,3,4,5
        const int s_init = sB[sg];
        const int s_end  = sB[sg - 1];
        const int s1 = s_init - 1, s0 = s_end;

        unsigned long long E2[16];                     // E row j, cols [g*32,+32)
        #pragma unroll
        for (int kk = 0; kk < 16; ++kk) {
            float lo = expf(T[j * LAB + g * 32 + 2 * kk]);
            float hi = expf(T[j * LAB + g * 32 + 2 * kk + 1]);
            PACK2(E2[kk], lo, hi);
        }

        const int chi = s1 >> 5, clo = s0 >> 5;
        PREFETCH(chi);
        if (chi > clo) PREFETCH(chi - 1);
        if (g == 0) {
            float uinit = __expf(encb[(size_t)s_init * LAB + j]);
            if (sg == 5) uinit *= expf(T[j * LAB + STOP_]);   // y: c * u_n
            p_sh[(s1 + 1) & 1][idx] = uinit;
        }
        if (chi > clo) CPW1(); else CPW0();
        __syncthreads();

        int s = s1;
        for (int c = chi; c >= clo; --c) {
            if (c < chi) {
                if (c > clo) { PREFETCH(c - 1); CPW1(); } else CPW0();
                __syncthreads();
            }
            const float* eb = e_sh[c & 1];
            const int slo = max(s0, c * CH);
            #pragma unroll 4
            for (; s >= slo; --s) {
                const float* pp = &p_sh[(s + 1) & 1][0];
                float u  = __expf(eb[(s - c * CH) * LAB + j]);
                float p0 = pp[0];
                int   e0 = ((__float_as_int(p0) >> 23) & 255) - 127;
                float sc = __int_as_float((127 - e0) << 23);
                Mi += e0;
                float us = (s == s0) ? sc : u * sc;    // boundary: apply E only
                const ulonglong2* pv =
                    reinterpret_cast<const ulonglong2*>(pp + g * 36);
                DOT_BODY(pv, q);
                if (g == 0) p_sh[s & 1][idx] = q * us;
                __syncthreads();
            }
        }
        par_out = s0 & 1;
    }

    if (g == 0) g_v[k][b][j] = p_sh[par_out][idx];
    if (tid == 0) g_mi8[k][b] = Mi;

    // ---- last-arriver combine (unlabeled output) ----
    __threadfence();
    __syncthreads();
    if (tid == 0) {
        int old = atomicAdd(&g_cnt[b], 1);
        win_sh = ((old & 7) == 7);         // 8th of the group this launch
    }
    __syncthreads();
    if (win_sh) {
        float d1 = 0, d2 = 0, d3 = 0, d4 = 0, d5 = 0, d6 = 0, d7 = 0;
        if (tid < LAB) {
            float xv  = __ldcg(&g_v[0][b][tid]);
            float f2v = __ldcg(&g_v[1][b][tid]);
            float f3v = __ldcg(&g_v[2][b][tid]);
            float f4v = __ldcg(&g_v[3][b][tid]);
            float g2v = __ldcg(&g_v[4][b][tid]);
            float g3v = __ldcg(&g_v[5][b][tid]);
            float g4v = __ldcg(&g_v[6][b][tid]);
            float yv  = __ldcg(&g_v[7][b][tid]);
            d1 = yv  * f4v;    // c^T M5 f4
            d2 = g4v * f3v;
            d3 = g3v * f2v;
            d4 = g2v * xv;     // g2^T M1 p0
            d5 = f2v;          // S2
            d6 = f3v;          // S3
            d7 = f4v;          // S4
        }
        #pragma unroll
        for (int m = 16; m; m >>= 1) {
            d1 += __shfl_xor_sync(0xffffffffu, d1, m);
            d2 += __shfl_xor_sync(0xffffffffu, d2, m);
            d3 += __shfl_xor_sync(0xffffffffu, d3, m);
            d4 += __shfl_xor_sync(0xffffffffu, d4, m);
            d5 += __shfl_xor_sync(0xffffffffu, d5, m);
            d6 += __shfl_xor_sync(0xffffffffu, d6, m);
            d7 += __shfl_xor_sync(0xffffffffu, d7, m);
        }
        if (tid == 0) {
            du[0]=d1; du[1]=d2; du[2]=d3; du[3]=d4; du[4]=d5; du[5]=d6; du[6]=d7;
        }
        if (tid == 32) {
            du[7]=d1; du[8]=d2; du[9]=d3; du[10]=d4; du[11]=d5; du[12]=d6; du[13]=d7;
        }
        __syncthreads();
        if (tid == 0) {
            float D1 = du[0] + du[7];
            float D2 = du[1] + du[8];
            float D3 = du[2] + du[9];
            float D4 = du[3] + du[10];
            float S2 = du[4] + du[11];
            float S3 = du[5] + du[12];
            float S4 = du[6] + du[13];
            // fwd-probe exponents cancel; keep x, g2, g3, g4, y
            int mtot = __ldcg(&g_mi8[0][b]) + __ldcg(&g_mi8[4][b])
                     + __ldcg(&g_mi8[5][b]) + __ldcg(&g_mi8[6][b])
                     + __ldcg(&g_mi8[7][b]);
            double lg = (double)logf(D1) + (double)logf(D2)
                      + (double)logf(D3) + (double)logf(D4)
                      - (double)logf(S2) - (double)logf(S3) - (double)logf(S4);
            out[b] = (float)((double)mtot * 0.6931471805599453 + lg);
        }
    }
}

extern "C" void kernel_launch(void* const* d_in, const int* in_sizes, int n_in,
                              void* d_out, int out_size)
{
    const float* enc  = (const float*)d_in[0];   // encoder_scores [32,512,64]
    const float* T    = (const float*)d_in[1];   // transition [64,64]
    const int*   lens = (const int*)  d_in[2];   // word_seq_lens [32]
    const int*   tags = (const int*)  d_in[3];   // tags [32,512]
    float* out = (float*)d_out;                  // [64]: unlabeled(32) ++ labeled(32)

    crf_fused_kernel<<<9 * BATCH, 128>>>(enc, T, lens, tags, out);
}

// round 12
// speedup vs baseline: 3.6364x; 1.0799x over previous
#include <cuda_runtime.h>
#include <cstdint>

#define BATCH  32
#define SEQ    512
#define LAB    64
#define START_ 61
#define STOP_  62
#define CH     32

#define FMA2(d,a,b,c)  asm("fma.rn.f32x2 %0, %1, %2, %3;" : "=l"(d) : "l"(a), "l"(b), "l"(c))
#define ADD2(d,a,b)    asm("add.rn.f32x2 %0, %1, %2;"     : "=l"(d) : "l"(a), "l"(b))
#define PACK2(d,lo,hi) asm("mov.b64 %0, {%1, %2};"        : "=l"(d) : "f"(lo), "f"(hi))
#define UNPACK2(lo,hi,s) asm("mov.b64 {%0, %1}, %2;"      : "=f"(lo), "=f"(hi) : "l"(s))
#define CPA(dst,src) asm volatile("cp.async.cg.shared.global [%0], [%1], 16;\n" :: "r"(dst), "l"(src))
#define CPC() asm volatile("cp.async.commit_group;\n")
#define CPW1() asm volatile("cp.async.wait_group 1;\n")
#define CPW0() asm volatile("cp.async.wait_group 0;\n")

// 64-thread chunk prefetch: 8 KB = 8 x (64 thr x 16 B)
#define PREFETCH(cc) do {                                                       \
    const float* _src = encb + (size_t)(cc) * CH * LAB + tid * 4;               \
    uint32_t _dst = (uint32_t)__cvta_generic_to_shared(&e_sh[(cc) & 1][tid*4]); \
    CPA(_dst,        _src);         CPA(_dst + 1024, _src + 256);               \
    CPA(_dst + 2048, _src + 512);   CPA(_dst + 3072, _src + 768);               \
    CPA(_dst + 4096, _src + 1024);  CPA(_dst + 5120, _src + 1280);              \
    CPA(_dst + 6144, _src + 1536);  CPA(_dst + 7168, _src + 1792);              \
    CPC();                                                                      \
} while (0)

// full 64-wide dot per thread: 16 broadcast LDS.128 + 32 FMA2 + tree
#define DOT64(PV, Q)                                                          \
    ulonglong2 w0 = (PV)[0],  w1 = (PV)[1],  w2 = (PV)[2],  w3 = (PV)[3];     \
    ulonglong2 w4 = (PV)[4],  w5 = (PV)[5],  w6 = (PV)[6],  w7 = (PV)[7];     \
    ulonglong2 w8 = (PV)[8],  w9 = (PV)[9],  wA = (PV)[10], wB = (PV)[11];    \
    ulonglong2 wC = (PV)[12], wD = (PV)[13], wE = (PV)[14], wF = (PV)[15];    \
    unsigned long long a0 = 0, a1 = 0, a2 = 0, a3 = 0;                        \
    FMA2(a0, w0.x, E2[ 0], a0); FMA2(a1, w0.y, E2[ 1], a1);                   \
    FMA2(a2, w1.x, E2[ 2], a2); FMA2(a3, w1.y, E2[ 3], a3);                   \
    FMA2(a0, w2.x, E2[ 4], a0); FMA2(a1, w2.y, E2[ 5], a1);                   \
    FMA2(a2, w3.x, E2[ 6], a2); FMA2(a3, w3.y, E2[ 7], a3);                   \
    FMA2(a0, w4.x, E2[ 8], a0); FMA2(a1, w4.y, E2[ 9], a1);                   \
    FMA2(a2, w5.x, E2[10], a2); FMA2(a3, w5.y, E2[11], a3);                   \
    FMA2(a0, w6.x, E2[12], a0); FMA2(a1, w6.y, E2[13], a1);                   \
    FMA2(a2, w7.x, E2[14], a2); FMA2(a3, w7.y, E2[15], a3);                   \
    FMA2(a0, w8.x, E2[16], a0); FMA2(a1, w8.y, E2[17], a1);                   \
    FMA2(a2, w9.x, E2[18], a2); FMA2(a3, w9.y, E2[19], a3);                   \
    FMA2(a0, wA.x, E2[20], a0); FMA2(a1, wA.y, E2[21], a1);                   \
    FMA2(a2, wB.x, E2[22], a2); FMA2(a3, wB.y, E2[23], a3);                   \
    FMA2(a0, wC.x, E2[24], a0); FMA2(a1, wC.y, E2[25], a1);                   \
    FMA2(a2, wD.x, E2[26], a2); FMA2(a3, wD.y, E2[27], a3);                   \
    FMA2(a0, wE.x, E2[28], a0); FMA2(a1, wE.y, E2[29], a1);                   \
    FMA2(a2, wF.x, E2[30], a2); FMA2(a3, wF.y, E2[31], a3);                   \
    unsigned long long s01, s23, sT;                                          \
    ADD2(s01, a0, a1); ADD2(s23, a2, a3); ADD2(sT, s01, s23);                 \
    float qlo, qhi; UNPACK2(qlo, qhi, sT);                                    \
    float Q = qlo + qhi

// chains per batch: 0=x(seg1) 1=f2 2=f3 3=f4 4=g2 5=g3 6=g4 7=y(seg5)
__device__ float g_v[8][BATCH][LAB];
__device__ int   g_mi8[8][BATCH];
__device__ int   g_cnt[BATCH];     // never reset; +8 per launch; (old&7)==7 -> combiner

__global__ __launch_bounds__(64, 1)
void crf_fused_kernel(const float* __restrict__ enc,   // [B,S,L]
                      const float* __restrict__ T,     // [L,L]
                      const int*   __restrict__ lens,  // [B]
                      const int*   __restrict__ tags,  // [B,S]
                      float*       __restrict__ out)   // [2*B]
{
    const int tid = threadIdx.x;

    // ================= LABELED blocks: 256..287 =================
    if (blockIdx.x >= 8 * BATCH) {
        const int b   = blockIdx.x - 8 * BATCH;
        const int len = lens[b];
        const float* encb = enc + (size_t)b * SEQ * LAB;
        const int*   tagb = tags + b * SEQ;
        __shared__ float lred[2];

        float lsum = 0.0f;
        for (int t = 1 + tid; t < len; t += 64) {
            int tg = tagb[t], tp = tagb[t - 1];
            lsum += T[tp * LAB + tg] + encb[(size_t)t * LAB + tg];
        }
        #pragma unroll
        for (int m = 16; m; m >>= 1)
            lsum += __shfl_xor_sync(0xffffffffu, lsum, m);
        if ((tid & 31) == 0) lred[tid >> 5] = lsum;
        __syncthreads();
        if (tid == 0) {
            int t0g = tagb[0];
            int eg  = tagb[len - 1];
            out[BATCH + b] = lred[0] + lred[1]
                           + T[START_ * LAB + t0g] + encb[t0g]
                           + T[eg * LAB + STOP_];
        }
        return;
    }

    // ================= CHAIN blocks: 0..255 (64 threads, col-per-thread) ======
    __shared__ __align__(16) float e_sh[2][CH * LAB];
    __shared__ __align__(16) float p_sh[2][LAB];
    __shared__ int win_sh;
    __shared__ float du[14];

    const int b   = blockIdx.x >> 3;
    const int k   = blockIdx.x & 7;
    const int len = lens[b];
    const int n   = len - 1;
    int sB[6];
    #pragma unroll
    for (int i = 0; i <= 5; ++i) sB[i] = (i * n) / 5;
    const float* encb = enc + (size_t)b * SEQ * LAB;

    int Mi = 0;
    int par_out;

    if (k <= 3) {
        // ---- FORWARD chains: p <- D_u E^T p over seg k+1 = (sB[k], sB[k+1]] ----
        const int t0 = sB[k] + 1;
        const int t1 = sB[k + 1];

        unsigned long long E2[32];                     // E column tid, all 64 rows
        #pragma unroll
        for (int kk = 0; kk < 32; ++kk) {
            float lo = expf(T[(2 * kk)     * LAB + tid]);
            float hi = expf(T[(2 * kk + 1) * LAB + tid]);
            PACK2(E2[kk], lo, hi);
        }

        const int c0 = t0 >> 5, c1 = t1 >> 5;
        PREFETCH(c0);
        if (c0 < c1) { PREFETCH(c0 + 1); CPW1(); } else CPW0();
        __syncthreads();
        if (k == 0) p_sh[0][tid] = expf(T[START_ * LAB + tid] + e_sh[0][tid]);
        else        p_sh[(t0 - 1) & 1][tid] = 1.0f;   // probe: ones
        __syncthreads();

        int t = t0;
        for (int c = c0; c <= c1; ++c) {
            if (c > c0) {
                if (c < c1) { PREFETCH(c + 1); CPW1(); } else CPW0();
                __syncthreads();
            }
            const float* eb = e_sh[c & 1];
            const int ttend = min((c + 1) * CH - 1, t1);
            #pragma unroll 4
            for (; t <= ttend; ++t) {
                const float* pp = &p_sh[(t - 1) & 1][0];
                const ulonglong2* pv = reinterpret_cast<const ulonglong2*>(pp);
                float u  = __expf(eb[(t - c * CH) * LAB + tid]);
                DOT64(pv, q);
                unsigned int p0b = (unsigned int)w0.x;     // p[0], broadcast-uniform
                int   e0 = (int)((p0b >> 23) & 255u) - 127;
                float sc = __int_as_float((127 - e0) << 23);
                Mi += e0;
                p_sh[t & 1][tid] = q * u * sc;
                __syncthreads();
            }
        }
        par_out = t1 & 1;
    } else {
        // ---- BACKWARD chains: w <- D_u E w over seg sg = (sB[sg-1], sB[sg]] ----
        const int sg = k - 2;                          // 2,3,4,5
        const int s_init = sB[sg];
        const int s_end  = sB[sg - 1];
        const int s1 = s_init - 1, s0 = s_end;

        unsigned long long E2[32];                     // E row tid, all 64 cols
        #pragma unroll
        for (int kk = 0; kk < 32; ++kk) {
            float lo = expf(T[tid * LAB + 2 * kk]);
            float hi = expf(T[tid * LAB + 2 * kk + 1]);
            PACK2(E2[kk], lo, hi);
        }

        const int chi = s1 >> 5, clo = s0 >> 5;
        PREFETCH(chi);
        if (chi > clo) PREFETCH(chi - 1);
        {
            float uinit = __expf(encb[(size_t)s_init * LAB + tid]);
            if (sg == 5) uinit *= expf(T[tid * LAB + STOP_]);   // y: c * u_n
            p_sh[(s1 + 1) & 1][tid] = uinit;
        }
        if (chi > clo) CPW1(); else CPW0();
        __syncthreads();

        int s = s1;
        for (int c = chi; c >= clo; --c) {
            if (c < chi) {
                if (c > clo) { PREFETCH(c - 1); CPW1(); } else CPW0();
                __syncthreads();
            }
            const float* eb = e_sh[c & 1];
            const int slo = max(s0, c * CH);
            #pragma unroll 4
            for (; s >= slo; --s) {
                const float* pp = &p_sh[(s + 1) & 1][0];
                const ulonglong2* pv = reinterpret_cast<const ulonglong2*>(pp);
                float u  = __expf(eb[(s - c * CH) * LAB + tid]);
                DOT64(pv, q);
                unsigned int p0b = (unsigned int)w0.x;
                int   e0 = (int)((p0b >> 23) & 255u) - 127;
                float sc = __int_as_float((127 - e0) << 23);
                Mi += e0;
                float us = (s == s0) ? sc : u * sc;    // boundary: apply E only
                p_sh[s & 1][tid] = q * us;
                __syncthreads();
            }
        }
        par_out = s0 & 1;
    }

    g_v[k][b][tid] = p_sh[par_out][tid];
    if (tid == 0) g_mi8[k][b] = Mi;

    // ---- last-arriver combine (unlabeled output) ----
    __threadfence();
    __syncthreads();
    if (tid == 0) {
        int old = atomicAdd(&g_cnt[b], 1);
        win_sh = ((old & 7) == 7);         // 8th of the group this launch
    }
    __syncthreads();
    if (win_sh) {
        float xv  = __ldcg(&g_v[0][b][tid]);
        float f2v = __ldcg(&g_v[1][b][tid]);
        float f3v = __ldcg(&g_v[2][b][tid]);
        float f4v = __ldcg(&g_v[3][b][tid]);
        float g2v = __ldcg(&g_v[4][b][tid]);
        float g3v = __ldcg(&g_v[5][b][tid]);
        float g4v = __ldcg(&g_v[6][b][tid]);
        float yv  = __ldcg(&g_v[7][b][tid]);
        float d1 = yv  * f4v;    // c^T M5 f4
        float d2 = g4v * f3v;
        float d3 = g3v * f2v;
        float d4 = g2v * xv;     // g2^T M1 p0
        float d5 = f2v, d6 = f3v, d7 = f4v;
        #pragma unroll
        for (int m = 16; m; m >>= 1) {
            d1 += __shfl_xor_sync(0xffffffffu, d1, m);
            d2 += __shfl_xor_sync(0xffffffffu, d2, m);
            d3 += __shfl_xor_sync(0xffffffffu, d3, m);
            d4 += __shfl_xor_sync(0xffffffffu, d4, m);
            d5 += __shfl_xor_sync(0xffffffffu, d5, m);
            d6 += __shfl_xor_sync(0xffffffffu, d6, m);
            d7 += __shfl_xor_sync(0xffffffffu, d7, m);
        }
        if (tid == 0) {
            du[0]=d1; du[1]=d2; du[2]=d3; du[3]=d4; du[4]=d5; du[5]=d6; du[6]=d7;
        }
        if (tid == 32) {
            du[7]=d1; du[8]=d2; du[9]=d3; du[10]=d4; du[11]=d5; du[12]=d6; du[13]=d7;
        }
        __syncthreads();
        if (tid == 0) {
            float D1 = du[0] + du[7];
            float D2 = du[1] + du[8];
            float D3 = du[2] + du[9];
            float D4 = du[3] + du[10];
            float S2 = du[4] + du[11];
            float S3 = du[5] + du[12];
            float S4 = du[6] + du[13];
            int mtot = __ldcg(&g_mi8[0][b]) + __ldcg(&g_mi8[4][b])
                     + __ldcg(&g_mi8[5][b]) + __ldcg(&g_mi8[6][b])
                     + __ldcg(&g_mi8[7][b]);
            double lg = (double)logf(D1) + (double)logf(D2)
                      + (double)logf(D3) + (double)logf(D4)
                      - (double)logf(S2) - (double)logf(S3) - (double)logf(S4);
            out[b] = (float)((double)mtot * 0.6931471805599453 + lg);
        }
    }
}

extern "C" void kernel_launch(void* const* d_in, const int* in_sizes, int n_in,
                              void* d_out, int out_size)
{
    const float* enc  = (const float*)d_in[0];   // encoder_scores [32,512,64]
    const float* T    = (const float*)d_in[1];   // transition [64,64]
    const int*   lens = (const int*)  d_in[2];   // word_seq_lens [32]
    const int*   tags = (const int*)  d_in[3];   // tags [32,512]
    float* out = (float*)d_out;                  // [64]: unlabeled(32) ++ labeled(32)

    crf_fused_kernel<<<9 * BATCH, 64>>>(enc, T, lens, tags, out);
}